// round 1
// baseline (speedup 1.0000x reference)
#include <cuda_runtime.h>
#include <cstdint>

// ---- static problem config ----
#define B_   2
#define N_   6
#define D_   48
#define FH_  16
#define FW_  44
#define C_   80
#define NX_  256
#define NY_  256
#define NPRIME (B_*N_*D_*FH_*FW_)       // 405504 points
#define NVOX   (B_*NY_*NX_)             // 131072 voxels (NZ=1)
#define SCR_F4 (NVOX*C_/4)              // 2,621,440 float4 (42 MB)
#define CVEC   (C_/4)                   // 20 float4 per point

// ---- device scratch (static globals: allowed; no allocation) ----
__device__ float4 g_scratch[SCR_F4];            // [B, NY, NX, C] accumulator
__device__ int    g_flat[NPRIME];               // per-point voxel index or -1
__device__ float  g_xf[B_*N_*24];               // per-(b,n): invPost[9], comb[9], trans[3], post_trans[3]

// ---------------------------------------------------------------------------
// 3x3 inverse via adjugate
__device__ __forceinline__ void inv3(const float* m, float* o) {
    float a=m[0], b=m[1], c=m[2];
    float d=m[3], e=m[4], f=m[5];
    float g=m[6], h=m[7], i=m[8];
    float A  =  (e*i - f*h);
    float Bc = -(d*i - f*g);
    float Cc =  (d*h - e*g);
    float det = a*A + b*Bc + c*Cc;
    float r = 1.0f / det;
    o[0] = A*r;            o[1] = (c*h - b*i)*r;  o[2] = (b*f - c*e)*r;
    o[3] = Bc*r;           o[4] = (a*i - c*g)*r;  o[5] = (c*d - a*f)*r;
    o[6] = Cc*r;           o[7] = (b*g - a*h)*r;  o[8] = (a*e - b*d)*r;
}

__global__ void setup_kernel(const float* __restrict__ rots,
                             const float* __restrict__ trans,
                             const float* __restrict__ intrins,
                             const float* __restrict__ post_rots,
                             const float* __restrict__ post_trans) {
    int t = threadIdx.x;
    if (t >= B_*N_) return;
    float invP[9], invK[9], comb[9];
    inv3(post_rots + t*9, invP);
    inv3(intrins  + t*9, invK);
    const float* R = rots + t*9;
    #pragma unroll
    for (int i = 0; i < 3; i++)
        #pragma unroll
        for (int j = 0; j < 3; j++) {
            float s = 0.0f;
            #pragma unroll
            for (int k = 0; k < 3; k++) s += R[i*3+k] * invK[k*3+j];
            comb[i*3+j] = s;
        }
    float* o = g_xf + t*24;
    #pragma unroll
    for (int i = 0; i < 9; i++) { o[i] = invP[i]; o[9+i] = comb[i]; }
    #pragma unroll
    for (int i = 0; i < 3; i++) { o[18+i] = trans[t*3+i]; o[21+i] = post_trans[t*3+i]; }
}

// ---------------------------------------------------------------------------
__global__ void zero_kernel() {
    int i = blockIdx.x * blockDim.x + threadIdx.x;
    if (i < SCR_F4) g_scratch[i] = make_float4(0.f, 0.f, 0.f, 0.f);
}

// ---------------------------------------------------------------------------
// Per-point geometry -> voxel flat index into the [B, NY, NX] grid (or -1).
__global__ void geom_kernel() {
    int p = blockIdx.x * blockDim.x + threadIdx.x;
    if (p >= NPRIME) return;

    int w  = p % FW_;
    int h  = (p / FW_) % FH_;
    int d  = (p / (FW_*FH_)) % D_;
    int bn = p / (FW_*FH_*D_);          // b*N + n
    int b  = bn / N_;

    const float* xf = g_xf + bn*24;

    // frustum point (matches numpy linspace / arange construction in fp32)
    float xs = (float)w * (float)(703.0 / 43.0);   // linspace(0, 703, 44)
    float ys = (float)h * 17.0f;                   // linspace(0, 255, 16)
    float ds = 2.0f + (float)(56.0 / 48.0) * (float)d;

    // p -= post_trans
    float px = xs - xf[21];
    float py = ys - xf[22];
    float pz = ds - xf[23];
    // p = inv(post_rots) @ p
    float qx = xf[0]*px + xf[1]*py + xf[2]*pz;
    float qy = xf[3]*px + xf[4]*py + xf[5]*pz;
    float qz = xf[6]*px + xf[7]*py + xf[8]*pz;
    // un-normalize pixel coords by depth
    qx *= qz; qy *= qz;
    // p = (rots @ inv(intrins)) @ p + trans
    float rx = xf[9 ]*qx + xf[10]*qy + xf[11]*qz + xf[18];
    float ry = xf[12]*qx + xf[13]*qy + xf[14]*qz + xf[19];
    float rz = xf[15]*qx + xf[16]*qy + xf[17]*qz + xf[20];

    // voxelize: ((geom - LOWER) / DX).astype(int32)  => C truncation-toward-zero
    int gx = (int)((rx - (-51.2f)) / 0.4f);
    int gy = (int)((ry - (-51.2f)) / 0.4f);
    int gz = (int)((rz - (-10.0f)) / 20.0f);

    bool kept = (gx >= 0) & (gx < NX_) & (gy >= 0) & (gy < NY_) & (gz >= 0) & (gz < 1);
    g_flat[p] = kept ? ((b * NY_ + gy) * NX_ + gx) : -1;
}

// ---------------------------------------------------------------------------
// Scatter: one thread per (point, float4-chunk). Coalesced x reads,
// 16B vector reductions into channels-last scratch (L2-resident).
__global__ void scatter_kernel(const float4* __restrict__ x4) {
    int t = blockIdx.x * blockDim.x + threadIdx.x;
    if (t >= NPRIME * CVEC) return;
    int p = t / CVEC;
    int k = t - p * CVEC;
    int flat = g_flat[p];
    if (flat < 0) return;
    float4 v = x4[t];                      // x is [NPRIME, C] contiguous
    float4* dst = g_scratch + (size_t)flat * CVEC + k;
    asm volatile("red.global.add.v4.f32 [%0], {%1, %2, %3, %4};"
                 :: "l"(dst), "f"(v.x), "f"(v.y), "f"(v.z), "f"(v.w)
                 : "memory");
}

// ---------------------------------------------------------------------------
// Transpose [B, NY, NX, C] -> [B, C, NY, NX].
// One block per (b, y, 32-wide x strip). SMEM tile padded to avoid conflicts.
__global__ void transpose_kernel(float* __restrict__ out) {
    __shared__ float tile[C_][33];
    int blk = blockIdx.x;
    int xb = blk & 7;                  // NX_/32 = 8 strips
    int y  = (blk >> 3) & (NY_ - 1);
    int b  = blk >> (3 + 8);
    int x0 = xb * 32;

    const float4* src = g_scratch + ((size_t)(b * NY_ + y) * NX_ + x0) * CVEC;
    for (int e = threadIdx.x; e < 32 * CVEC; e += blockDim.x) {
        int xl = e / CVEC;
        int k  = e - xl * CVEC;
        float4 v = src[xl * CVEC + k];
        tile[4*k + 0][xl] = v.x;
        tile[4*k + 1][xl] = v.y;
        tile[4*k + 2][xl] = v.z;
        tile[4*k + 3][xl] = v.w;
    }
    __syncthreads();

    float* ob = out + (size_t)b * C_ * NY_ * NX_ + (size_t)y * NX_ + x0;
    for (int e = threadIdx.x; e < C_ * 32; e += blockDim.x) {
        int c  = e >> 5;
        int xl = e & 31;
        ob[(size_t)c * (NY_ * NX_) + xl] = tile[c][xl];
    }
}

// ---------------------------------------------------------------------------
extern "C" void kernel_launch(void* const* d_in, const int* in_sizes, int n_in,
                              void* d_out, int out_size) {
    const float* x          = (const float*)d_in[0];
    const float* rots       = (const float*)d_in[1];
    const float* trans      = (const float*)d_in[2];
    const float* intrins    = (const float*)d_in[3];
    const float* post_rots  = (const float*)d_in[4];
    const float* post_trans = (const float*)d_in[5];
    float* out = (float*)d_out;

    setup_kernel<<<1, 32>>>(rots, trans, intrins, post_rots, post_trans);
    zero_kernel<<<(SCR_F4 + 255) / 256, 256>>>();
    geom_kernel<<<(NPRIME + 255) / 256, 256>>>();
    scatter_kernel<<<(NPRIME * CVEC + 255) / 256, 256>>>((const float4*)x);
    transpose_kernel<<<B_ * NY_ * (NX_ / 32), 256>>>(out);
}